// round 7
// baseline (speedup 1.0000x reference)
#include <cuda_runtime.h>
#include <cuda_bf16.h>

#define LSEQ 2048
#define DMODEL 1024
#define NTOK 4096
#define NH 16
#define DH 64
typedef __nv_bfloat16 bf16;
typedef __nv_bfloat162 bf162;

// ---------------- device scratch ----------------
__device__ bf16 g_Xhi[(size_t)NTOK * DMODEL], g_Xlo[(size_t)NTOK * DMODEL];
__device__ bf16 g_Wth[4][(size_t)DMODEL * DMODEL], g_Wtl[4][(size_t)DMODEL * DMODEL];
__device__ bf16 g_Qhi[(size_t)NTOK * DMODEL], g_Qlo[(size_t)NTOK * DMODEL];
__device__ bf16 g_Khi[(size_t)NTOK * DMODEL], g_Klo[(size_t)NTOK * DMODEL];
__device__ bf16 g_Vth[(size_t)NTOK * DMODEL], g_Vtl[(size_t)NTOK * DMODEL]; // [B,H,Dh,L]
__device__ bf16 g_Ohi[(size_t)NTOK * DMODEL], g_Olo[(size_t)NTOK * DMODEL];

// ---------------- helpers ----------------
__device__ __forceinline__ unsigned ldu(const bf16* p) {
    return *reinterpret_cast<const unsigned*>(p);
}
__device__ __forceinline__ void ldsm4(unsigned* d, const bf16* p) {
    unsigned a = (unsigned)__cvta_generic_to_shared(p);
    asm volatile("ldmatrix.sync.aligned.m8n8.x4.shared.b16 {%0,%1,%2,%3}, [%4];"
        : "=r"(d[0]), "=r"(d[1]), "=r"(d[2]), "=r"(d[3]) : "r"(a));
}
__device__ __forceinline__ void split2u(float x, float y, unsigned& uh, unsigned& ul) {
    bf162 h, l;
    h.x = __float2bfloat16(x); h.y = __float2bfloat16(y);
    l.x = __float2bfloat16(x - __bfloat162float(h.x));
    l.y = __float2bfloat16(y - __bfloat162float(h.y));
    uh = *reinterpret_cast<unsigned*>(&h);
    ul = *reinterpret_cast<unsigned*>(&l);
}
__device__ __forceinline__ void mma16(float* c, const unsigned* a, const unsigned* b) {
    asm volatile(
        "mma.sync.aligned.m16n8k16.row.col.f32.bf16.bf16.f32 "
        "{%0,%1,%2,%3},{%4,%5,%6,%7},{%8,%9},{%0,%1,%2,%3};"
        : "+f"(c[0]), "+f"(c[1]), "+f"(c[2]), "+f"(c[3])
        : "r"(a[0]), "r"(a[1]), "r"(a[2]), "r"(a[3]), "r"(b[0]), "r"(b[1]));
}
__device__ __forceinline__ void cpa(bf16* s, const bf16* g) {
    unsigned sa = (unsigned)__cvta_generic_to_shared(s);
    asm volatile("cp.async.cg.shared.global [%0], [%1], 16;" :: "r"(sa), "l"(g));
}
#define CP_COMMIT() asm volatile("cp.async.commit_group;")
__device__ __forceinline__ void cp_wait1() { asm volatile("cp.async.wait_group 1;"); }
__device__ __forceinline__ void cp_wait0() { asm volatile("cp.async.wait_group 0;"); }

// ---------------- split X ----------------
__global__ __launch_bounds__(256) void split_x(const float* __restrict__ src) {
    int i = blockIdx.x * 256 + threadIdx.x;
    float2 v = reinterpret_cast<const float2*>(src)[i];
    unsigned uh, ul;
    split2u(v.x, v.y, uh, ul);
    reinterpret_cast<unsigned*>(g_Xhi)[i] = uh;
    reinterpret_cast<unsigned*>(g_Xlo)[i] = ul;
}

// ---------------- transpose+split weight [K][N] -> Wt[N][K] ----------------
__global__ __launch_bounds__(256) void tsplit(const float* __restrict__ W, int wsel) {
    __shared__ float t[32][33];
    const int n0 = blockIdx.x * 32, k0 = blockIdx.y * 32;
    const int tx = threadIdx.x & 31, ty = threadIdx.x >> 5;
    #pragma unroll
    for (int i = 0; i < 4; i++)
        t[ty + i * 8][tx] = W[(size_t)(k0 + ty + i * 8) * DMODEL + n0 + tx];
    __syncthreads();
    bf16* th = g_Wth[wsel];
    bf16* tl = g_Wtl[wsel];
    #pragma unroll
    for (int i = 0; i < 4; i++) {
        int n = ty + i * 8;
        float v = t[tx][n];
        bf16 h = __float2bfloat16(v);
        th[(size_t)(n0 + n) * DMODEL + k0 + tx] = h;
        tl[(size_t)(n0 + n) * DMODEL + k0 + tx] = __float2bfloat16(v - __bfloat162float(h));
    }
}

// ---------------- bf16x3 GEMM: C[4096][1024] = A * Bt^T ----------------
// 128x128x32 tiles, 256 thr, 8 warps (2Mx4N), warp 64x32. LDSM operand loads.
#define ASTR 40
#define STAGE (4 * 128 * ASTR)

template <int MODE>
__global__ __launch_bounds__(256) void gemm_kernel(int asel, int wsel, int osel,
                                                   float* __restrict__ Cf) {
    extern __shared__ __align__(16) bf16 sm[];
    const bf16* Ah = asel ? g_Ohi : g_Xhi;
    const bf16* Al = asel ? g_Olo : g_Xlo;
    const bf16* Bh = g_Wth[wsel];
    const bf16* Bl = g_Wtl[wsel];

    const int tid = threadIdx.x, lane = tid & 31, wid = tid >> 5;
    const int r = lane >> 2, q = lane & 3;
    const int g = lane >> 3, rr = lane & 7;
    const int wm = (wid & 1) * 64, wn = (wid >> 1) * 32;
    const int row0 = blockIdx.y * 128, col0 = blockIdx.x * 128;

    float acc[4][4][4] = {};

    auto load = [&](int k0, int st) {
        bf16* sb = sm + st * STAGE;
        #pragma unroll
        for (int i = 0; i < 2; i++) {
            int idx = tid * 2 + i;
            int rw = idx >> 2, c = idx & 3;
            const bf16* ga  = Ah + (size_t)(row0 + rw) * DMODEL + k0 + c * 8;
            const bf16* gal = Al + (size_t)(row0 + rw) * DMODEL + k0 + c * 8;
            const bf16* gb  = Bh + (size_t)(col0 + rw) * DMODEL + k0 + c * 8;
            const bf16* gbl = Bl + (size_t)(col0 + rw) * DMODEL + k0 + c * 8;
            cpa(sb + rw * ASTR + c * 8, ga);
            cpa(sb + 128 * ASTR + rw * ASTR + c * 8, gal);
            cpa(sb + 2 * 128 * ASTR + rw * ASTR + c * 8, gb);
            cpa(sb + 3 * 128 * ASTR + rw * ASTR + c * 8, gbl);
        }
    };

    load(0, 0); CP_COMMIT();
    load(32, 1); CP_COMMIT();

    for (int kt = 0; kt < 32; kt++) {
        if (kt < 31) cp_wait1(); else cp_wait0();
        __syncthreads();
        const int st = kt & 1;
        const bf16* ah = sm + st * STAGE + wm * ASTR;
        const bf16* bh = sm + st * STAGE + 2 * 128 * ASTR + wn * ASTR;
        #pragma unroll
        for (int ks = 0; ks < 2; ks++) {
            unsigned afh[4][4], afl[4][4];
            #pragma unroll
            for (int mt = 0; mt < 4; mt++) {
                const bf16* pa = ah + (mt * 16 + (g & 1) * 8 + rr) * ASTR + ks * 16 + (g >> 1) * 8;
                ldsm4(afh[mt], pa);
                ldsm4(afl[mt], pa + 128 * ASTR);
            }
            unsigned bfh[4][2], bfl[4][2];
            #pragma unroll
            for (int p = 0; p < 2; p++) {
                const bf16* pb = bh + (p * 16 + (g >> 1) * 8 + rr) * ASTR + ks * 16 + (g & 1) * 8;
                unsigned t4[4];
                ldsm4(t4, pb);
                bfh[2*p][0] = t4[0]; bfh[2*p][1] = t4[1];
                bfh[2*p+1][0] = t4[2]; bfh[2*p+1][1] = t4[3];
                ldsm4(t4, pb + 128 * ASTR);
                bfl[2*p][0] = t4[0]; bfl[2*p][1] = t4[1];
                bfl[2*p+1][0] = t4[2]; bfl[2*p+1][1] = t4[3];
            }
            #pragma unroll
            for (int nt = 0; nt < 4; nt++) {
                #pragma unroll
                for (int mt = 0; mt < 4; mt++) {
                    mma16(acc[mt][nt], afh[mt], bfh[nt]);
                    mma16(acc[mt][nt], afh[mt], bfl[nt]);
                    mma16(acc[mt][nt], afl[mt], bfh[nt]);
                }
            }
        }
        __syncthreads();
        if (kt + 2 < 32) { load((kt + 2) * 32, st); CP_COMMIT(); }
    }

    // epilogue
    #pragma unroll
    for (int mt = 0; mt < 4; mt++) {
        #pragma unroll
        for (int nt = 0; nt < 4; nt++) {
            const int m = row0 + wm + mt * 16 + r;
            const int n = col0 + wn + nt * 8 + 2 * q;
            if (MODE == 0) {
                *reinterpret_cast<float2*>(Cf + (size_t)m * DMODEL + n) =
                    make_float2(acc[mt][nt][0], acc[mt][nt][1]);
                *reinterpret_cast<float2*>(Cf + (size_t)(m + 8) * DMODEL + n) =
                    make_float2(acc[mt][nt][2], acc[mt][nt][3]);
            } else {
                const int b = m >> 11, l = m & (LSEQ - 1);
                const int h = n >> 6, e = n & 63;
                unsigned h01, l01, h23, l23;
                split2u(acc[mt][nt][0], acc[mt][nt][1], h01, l01);
                split2u(acc[mt][nt][2], acc[mt][nt][3], h23, l23);
                if (MODE == 1) {
                    bf16* Ch = osel ? g_Khi : g_Qhi;
                    bf16* Cl = osel ? g_Klo : g_Qlo;
                    size_t a0 = ((((size_t)b * NH + h) * LSEQ + l) * DH + e) >> 1;
                    size_t a1 = ((((size_t)b * NH + h) * LSEQ + l + 8) * DH + e) >> 1;
                    reinterpret_cast<unsigned*>(Ch)[a0] = h01;
                    reinterpret_cast<unsigned*>(Cl)[a0] = l01;
                    reinterpret_cast<unsigned*>(Ch)[a1] = h23;
                    reinterpret_cast<unsigned*>(Cl)[a1] = l23;
                } else {
                    bf162 H01 = *reinterpret_cast<bf162*>(&h01);
                    bf162 L01 = *reinterpret_cast<bf162*>(&l01);
                    bf162 H23 = *reinterpret_cast<bf162*>(&h23);
                    bf162 L23 = *reinterpret_cast<bf162*>(&l23);
                    size_t base = (((size_t)b * NH + h) * DH + e) * LSEQ + l;
                    g_Vth[base] = H01.x;            g_Vtl[base] = L01.x;
                    g_Vth[base + LSEQ] = H01.y;     g_Vtl[base + LSEQ] = L01.y;
                    g_Vth[base + 8] = H23.x;        g_Vtl[base + 8] = L23.x;
                    g_Vth[base + LSEQ + 8] = H23.y; g_Vtl[base + LSEQ + 8] = L23.y;
                }
            }
        }
    }
}

// ---------------- flash attention (bf16x3, LDSM, double-buffered K/V) ----------------
#define TILE (64 * 72)
#define ASTAGE (4 * TILE)

__global__ __launch_bounds__(256) void attn_kernel() {
    extern __shared__ __align__(16) bf16 smd[];

    const int tid = threadIdx.x, lane = tid & 31, wid = tid >> 5;
    const int r = lane >> 2, q = lane & 3;
    const int g = lane >> 3, rr = lane & 7;
    const int qt = blockIdx.x, h = blockIdx.y, b = blockIdx.z;
    const int q0 = qt * 128, wm = wid * 16;
    const int rowg0 = q0 + wm + r, rowg1 = rowg0 + 8;

    const bf16* Qh = g_Qhi + ((size_t)(b * NH + h) * LSEQ) * DH;
    const bf16* Ql = g_Qlo + ((size_t)(b * NH + h) * LSEQ) * DH;
    const bf16* Kh = g_Khi + ((size_t)(b * NH + h) * LSEQ) * DH;
    const bf16* Kl = g_Klo + ((size_t)(b * NH + h) * LSEQ) * DH;
    const bf16* Vh = g_Vth + ((size_t)(b * NH + h) * DH) * LSEQ;
    const bf16* Vl = g_Vtl + ((size_t)(b * NH + h) * DH) * LSEQ;

    // Q fragments (register resident)
    unsigned qh[4][4], ql[4][4];
    #pragma unroll
    for (int kk = 0; kk < 4; kk++) {
        const bf16* p = Qh + (size_t)rowg0 * DH + kk * 16 + 2 * q;
        const bf16* pl = Ql + (size_t)rowg0 * DH + kk * 16 + 2 * q;
        qh[kk][0] = ldu(p);      qh[kk][1] = ldu(p + 8 * DH);
        qh[kk][2] = ldu(p + 8);  qh[kk][3] = ldu(p + 8 * DH + 8);
        ql[kk][0] = ldu(pl);     ql[kk][1] = ldu(pl + 8 * DH);
        ql[kk][2] = ldu(pl + 8); ql[kk][3] = ldu(pl + 8 * DH + 8);
    }

    const int njv = 2 * qt + 2;

    auto loadkv = [&](int j, int st) {
        bf16* base = smd + st * ASTAGE;
        const int k0 = j * 64;
        #pragma unroll
        for (int t = 0; t < 8; t++) {
            int idx = t * 256 + tid;
            int tile = idx >> 9, r2 = (idx >> 3) & 63, c = (idx & 7) * 8;
            bf16* dst = base + tile * TILE + r2 * 72 + c;
            const bf16* src;
            if (tile == 0)      src = Kh + (size_t)(k0 + r2) * DH + c;
            else if (tile == 1) src = Kl + (size_t)(k0 + r2) * DH + c;
            else if (tile == 2) src = Vh + (size_t)r2 * LSEQ + k0 + c;
            else                src = Vl + (size_t)r2 * LSEQ + k0 + c;
            cpa(dst, src);
        }
    };

    float oacc[8][4] = {};
    float m0 = -1e30f, m1 = -1e30f, l0 = 0.f, l1 = 0.f;

    loadkv(0, 0); CP_COMMIT();
    loadkv(1, 1); CP_COMMIT();

    for (int j = 0; j < njv; j++) {
        const int k0 = j * 64;
        if (j < njv - 1) cp_wait1(); else cp_wait0();
        __syncthreads();

        if (k0 <= q0 + wm + 15) {
            const bf16* sK = smd + (j & 1) * ASTAGE;
            const bf16* sV = sK + 2 * TILE;

            // S = Q K^T (16 x 64)
            float sacc[8][4] = {};
            #pragma unroll
            for (int kk = 0; kk < 4; kk++) {
                unsigned bh2[8][2], bl2[8][2];
                #pragma unroll
                for (int p = 0; p < 4; p++) {
                    const bf16* pk = sK + (p * 16 + (g >> 1) * 8 + rr) * 72 + kk * 16 + (g & 1) * 8;
                    unsigned t4[4];
                    ldsm4(t4, pk);
                    bh2[2*p][0] = t4[0]; bh2[2*p][1] = t4[1];
                    bh2[2*p+1][0] = t4[2]; bh2[2*p+1][1] = t4[3];
                    ldsm4(t4, pk + TILE);
                    bl2[2*p][0] = t4[0]; bl2[2*p][1] = t4[1];
                    bl2[2*p+1][0] = t4[2]; bl2[2*p+1][1] = t4[3];
                }
                #pragma unroll
                for (int nt = 0; nt < 8; nt++) {
                    mma16(sacc[nt], qh[kk], bh2[nt]);
                    mma16(sacc[nt], qh[kk], bl2[nt]);
                    mma16(sacc[nt], ql[kk], bh2[nt]);
                }
            }

            // scale + causal mask
            #pragma unroll
            for (int nt = 0; nt < 8; nt++) {
                const int c0 = k0 + nt * 8 + 2 * q, c1 = c0 + 1;
                sacc[nt][0] = (c0 > rowg0) ? -1e30f : sacc[nt][0] * 0.125f;
                sacc[nt][1] = (c1 > rowg0) ? -1e30f : sacc[nt][1] * 0.125f;
                sacc[nt][2] = (c0 > rowg1) ? -1e30f : sacc[nt][2] * 0.125f;
                sacc[nt][3] = (c1 > rowg1) ? -1e30f : sacc[nt][3] * 0.125f;
            }

            // online softmax
            float mx0 = -1e30f, mx1 = -1e30f;
            #pragma unroll
            for (int nt = 0; nt < 8; nt++) {
                mx0 = fmaxf(mx0, fmaxf(sacc[nt][0], sacc[nt][1]));
                mx1 = fmaxf(mx1, fmaxf(sacc[nt][2], sacc[nt][3]));
            }
            #pragma unroll
            for (int off = 1; off <= 2; off <<= 1) {
                mx0 = fmaxf(mx0, __shfl_xor_sync(0xffffffffu, mx0, off));
                mx1 = fmaxf(mx1, __shfl_xor_sync(0xffffffffu, mx1, off));
            }
            const float mn0 = fmaxf(m0, mx0), mn1 = fmaxf(m1, mx1);
            const float es0 = __expf(m0 - mn0), es1 = __expf(m1 - mn1);
            float ls0 = 0.f, ls1 = 0.f;
            #pragma unroll
            for (int nt = 0; nt < 8; nt++) {
                sacc[nt][0] = __expf(sacc[nt][0] - mn0);
                sacc[nt][1] = __expf(sacc[nt][1] - mn0);
                sacc[nt][2] = __expf(sacc[nt][2] - mn1);
                sacc[nt][3] = __expf(sacc[nt][3] - mn1);
                ls0 += sacc[nt][0] + sacc[nt][1];
                ls1 += sacc[nt][2] + sacc[nt][3];
            }
            #pragma unroll
            for (int off = 1; off <= 2; off <<= 1) {
                ls0 += __shfl_xor_sync(0xffffffffu, ls0, off);
                ls1 += __shfl_xor_sync(0xffffffffu, ls1, off);
            }
            m0 = mn0; m1 = mn1;
            l0 = l0 * es0 + ls0;
            l1 = l1 * es1 + ls1;
            #pragma unroll
            for (int nt = 0; nt < 8; nt++) {
                oacc[nt][0] *= es0; oacc[nt][1] *= es0;
                oacc[nt][2] *= es1; oacc[nt][3] *= es1;
            }

            // O += P V
            #pragma unroll
            for (int kk = 0; kk < 4; kk++) {
                unsigned pah[4], pal[4];
                split2u(sacc[2*kk][0],   sacc[2*kk][1],   pah[0], pal[0]);
                split2u(sacc[2*kk][2],   sacc[2*kk][3],   pah[1], pal[1]);
                split2u(sacc[2*kk+1][0], sacc[2*kk+1][1], pah[2], pal[2]);
                split2u(sacc[2*kk+1][2], sacc[2*kk+1][3], pah[3], pal[3]);
                unsigned bh2[8][2], bl2[8][2];
                #pragma unroll
                for (int p = 0; p < 4; p++) {
                    const bf16* pv = sV + (p * 16 + (g >> 1) * 8 + rr) * 72 + kk * 16 + (g & 1) * 8;
                    unsigned t4[4];
                    ldsm4(t4, pv);
                    bh2[2*p][0] = t4[0]; bh2[2*p][1] = t4[1];
                    bh2[2*p+1][0] = t4[2]; bh2[2*p+1][1] = t4[3];
                    ldsm4(t4, pv + TILE);
                    bl2[2*p][0] = t4[0]; bl2[2*p][1] = t4[1];
                    bl2[2*p+1][0] = t4[2]; bl2[2*p+1][1] = t4[3];
                }
                #pragma unroll
                for (int nt = 0; nt < 8; nt++) {
                    mma16(oacc[nt], pah, bh2[nt]);
                    mma16(oacc[nt], pah, bl2[nt]);
                    mma16(oacc[nt], pal, bh2[nt]);
                }
            }
        }

        __syncthreads();
        if (j + 2 < njv) { loadkv(j + 2, j & 1); CP_COMMIT(); }
    }

    // epilogue: O/l -> split bf16 [B,L,H,Dh]
    const float i0 = 1.f / l0, i1 = 1.f / l1;
    #pragma unroll
    for (int nt = 0; nt < 8; nt++) {
        unsigned h01, l01, h23, l23;
        split2u(oacc[nt][0] * i0, oacc[nt][1] * i0, h01, l01);
        split2u(oacc[nt][2] * i1, oacc[nt][3] * i1, h23, l23);
        const int e = nt * 8 + 2 * q;
        size_t a0 = (((size_t)(b * LSEQ + rowg0) * NH + h) * DH + e) >> 1;
        size_t a1 = (((size_t)(b * LSEQ + rowg1) * NH + h) * DH + e) >> 1;
        reinterpret_cast<unsigned*>(g_Ohi)[a0] = h01;
        reinterpret_cast<unsigned*>(g_Olo)[a0] = l01;
        reinterpret_cast<unsigned*>(g_Ohi)[a1] = h23;
        reinterpret_cast<unsigned*>(g_Olo)[a1] = l23;
    }
}

// ---------------------------------------------------------------------------
extern "C" void kernel_launch(void* const* d_in, const int* in_sizes, int n_in,
                              void* d_out, int out_size)
{
    const float* x = (const float*)d_in[0];
    float* out = (float*)d_out;

    const int gsm = 2 * STAGE * (int)sizeof(bf16);     // 80KB
    const int asm_ = 2 * ASTAGE * (int)sizeof(bf16);   // 72KB
    cudaFuncSetAttribute(gemm_kernel<0>, cudaFuncAttributeMaxDynamicSharedMemorySize, gsm);
    cudaFuncSetAttribute(gemm_kernel<1>, cudaFuncAttributeMaxDynamicSharedMemorySize, gsm);
    cudaFuncSetAttribute(gemm_kernel<2>, cudaFuncAttributeMaxDynamicSharedMemorySize, gsm);
    cudaFuncSetAttribute(attn_kernel, cudaFuncAttributeMaxDynamicSharedMemorySize, asm_);

    split_x<<<NTOK * DMODEL / 512, 256>>>(x);
    for (int w = 0; w < 4; w++)
        tsplit<<<dim3(32, 32), 256>>>((const float*)d_in[1 + w], w);

    dim3 gg(8, 32);
    gemm_kernel<1><<<gg, 256, gsm>>>(0, 0, 0, nullptr);  // Q
    gemm_kernel<1><<<gg, 256, gsm>>>(0, 1, 1, nullptr);  // K
    gemm_kernel<2><<<gg, 256, gsm>>>(0, 2, 0, nullptr);  // V (transposed)

    attn_kernel<<<dim3(LSEQ / 128, NH, 2), 256, asm_>>>();

    gemm_kernel<0><<<gg, 256, gsm>>>(1, 3, 0, out);      // out projection
}